// round 4
// baseline (speedup 1.0000x reference)
#include <cuda_runtime.h>

#define U  2048
#define BB 16
#define D  32

// ---------------- device scratch (no allocations allowed) ----------------
__device__ float g_coldenom[3 * BB * U];        // Σ_i exp(s_ij) per (p,b,j)
__device__ float g_O2[3 * BB * D];              // O2[b,0,:] per (p,b)
__device__ float g_Bi[BB * 3 * 2 * D];          // Bi [b][pair][64]
__device__ __align__(16) float g_CCA[BB * 2 * D];

// ---------------- K0: zero accumulators (graph-replay safe) ----------------
__global__ void k_zero() {
    int i = blockIdx.x * blockDim.x + threadIdx.x;
    if (i < 3 * BB * U) g_coldenom[i] = 0.f;
    if (i < 3 * BB * D) g_O2[i] = 0.f;
}

// ---------------- K1: main pass — exp row/col sums + O2 ----------------
__device__ __forceinline__ void load_tile_kmajor(const float* __restrict__ base,
                                                 int row0, float (*s)[128], int t) {
    int r = t & 127, h = t >> 7;
    const float4* src = (const float4*)(base + (size_t)(row0 + r) * D + h * 16);
    float4 x0 = src[0], x1 = src[1], x2 = src[2], x3 = src[3];
    int kb = h * 16;
    s[kb + 0][r] = x0.x;  s[kb + 1][r] = x0.y;  s[kb + 2][r] = x0.z;  s[kb + 3][r] = x0.w;
    s[kb + 4][r] = x1.x;  s[kb + 5][r] = x1.y;  s[kb + 6][r] = x1.z;  s[kb + 7][r] = x1.w;
    s[kb + 8][r] = x2.x;  s[kb + 9][r] = x2.y;  s[kb +10][r] = x2.z;  s[kb +11][r] = x2.w;
    s[kb +12][r] = x3.x;  s[kb +13][r] = x3.y;  s[kb +14][r] = x3.z;  s[kb +15][r] = x3.w;
}

__global__ void __launch_bounds__(256, 2)
k_main(const float* __restrict__ A, const float* __restrict__ V,
       const float* __restrict__ L) {
    const int tileI = blockIdx.x;   // 0..15  (rows i0 = tileI*128)
    const int b     = blockIdx.y;   // 0..15
    const int p     = blockIdx.z;   // 0:AV 1:AL 2:VL
    const float* f1 = (p == 2 ? V : A) + (size_t)b * U * D;
    const float* f2 = (p == 0 ? V : L) + (size_t)b * U * D;

    __shared__ float s1[D][128];      // f1 tile, k-major
    __shared__ float s2[D][128];      // f2 tile, k-major
    __shared__ float scol[16][128];   // per-ty partial column sums
    __shared__ float wbuf[128];       // exp(s_i0)/rowsum_i
    __shared__ float red[8][32];

    const int t  = threadIdx.x;
    const int tx = t & 15;            // column group: j = tx + 16*c
    const int ty = t >> 4;            // row group:    i = ty + 16*r

    load_tile_kmajor(f1, tileI * 128, s1, t);

    float rowsum[8];
    float e0[8];
#pragma unroll
    for (int r = 0; r < 8; r++) { rowsum[r] = 0.f; e0[r] = 0.f; }

    for (int jt = 0; jt < 16; ++jt) {
        __syncthreads();              // protect s2/scol from previous iter readers
        load_tile_kmajor(f2, jt * 128, s2, t);
        __syncthreads();

        float acc[8][8];
#pragma unroll
        for (int r = 0; r < 8; r++)
#pragma unroll
            for (int c = 0; c < 8; c++) acc[r][c] = 0.f;

#pragma unroll 4
        for (int k = 0; k < D; k++) {
            float af[8], bf[8];
#pragma unroll
            for (int r = 0; r < 8; r++) af[r] = s1[k][ty + 16 * r];
#pragma unroll
            for (int c = 0; c < 8; c++) bf[c] = s2[k][tx + 16 * c];
#pragma unroll
            for (int r = 0; r < 8; r++)
#pragma unroll
                for (int c = 0; c < 8; c++) acc[r][c] += af[r] * bf[c];
        }

        float cs[8];
#pragma unroll
        for (int c = 0; c < 8; c++) cs[c] = 0.f;
#pragma unroll
        for (int r = 0; r < 8; r++) {
#pragma unroll
            for (int c = 0; c < 8; c++) {
                float e = __expf(acc[r][c]);
                rowsum[r] += e;
                cs[c] += e;
            }
        }
        if (jt == 0 && tx == 0) {     // column j==0 lives at (tx=0, c=0)
#pragma unroll
            for (int r = 0; r < 8; r++) e0[r] = __expf(acc[r][0]);
        }
#pragma unroll
        for (int c = 0; c < 8; c++) scol[ty][tx + 16 * c] = cs[c];
        __syncthreads();
        if (t < 128) {
            float s = 0.f;
#pragma unroll
            for (int y = 0; y < 16; y++) s += scol[y][t];
            atomicAdd(&g_coldenom[(p * BB + b) * U + jt * 128 + t], s);
        }
    }

    // row denominators: reduce across the 16 tx lanes (same half-warp)
#pragma unroll
    for (int r = 0; r < 8; r++) {
        float s = rowsum[r];
#pragma unroll
        for (int o = 8; o; o >>= 1) s += __shfl_xor_sync(0xffffffffu, s, o, 16);
        if (tx == 0) wbuf[ty + 16 * r] = e0[r] / s;
    }
    __syncthreads();

    // partial O2[d] = Σ_i w_i * f1[i][d]   (s1 is [d][i])
    {
        int d = t & 31, ch = t >> 5;
        float po = 0.f;
#pragma unroll
        for (int ii = 0; ii < 16; ii++) {
            int i = ch * 16 + ii;
            po += wbuf[i] * s1[d][i];
        }
        red[ch][d] = po;
    }
    __syncthreads();
    if (t < 32) {
        float s = 0.f;
#pragma unroll
        for (int ch = 0; ch < 8; ch++) s += red[ch][t];
        atomicAdd(&g_O2[(p * BB + b) * D + t], s);
    }
}

// ---------------- K2: finish O1, build Bi ----------------
__global__ void k_stage2(const float* __restrict__ A, const float* __restrict__ V,
                         const float* __restrict__ L) {
    const int p = blockIdx.x, b = blockIdx.y;
    const float* f1 = (p == 2 ? V : A) + (size_t)b * U * D;
    const float* f2 = (p == 0 ? V : L) + (size_t)b * U * D;
    const int t = threadIdx.x, lane = t & 31, w = t >> 5;
    __shared__ float red[8][32];

    const float f10 = f1[lane];                 // f1 row 0, element `lane`
    const float* cd = &g_coldenom[(p * BB + b) * U];
    float acc = 0.f;
    for (int j = w; j < U; j += 8) {
        float f2v = f2[(size_t)j * D + lane];
        float prod = f10 * f2v;
#pragma unroll
        for (int o = 16; o; o >>= 1) prod += __shfl_xor_sync(0xffffffffu, prod, o);
        float wgt = __expf(prod) / cd[j];
        acc += wgt * f2v;
    }
    red[w][lane] = acc;
    __syncthreads();
    if (t < 32) {
        float o1 = 0.f;
#pragma unroll
        for (int ww = 0; ww < 8; ww++) o1 += red[ww][t];
        float f20 = f2[t];
        g_Bi[b * 192 + p * 64 + t]      = o1 * f10;                       // A1[b,0,:]
        g_Bi[b * 192 + p * 64 + 32 + t] = g_O2[(p * BB + b) * D + t] * f20; // A2[b,0,:]
    }
}

// ---------------- K3: FC head + batch softmax + CCA ----------------
__global__ void k_head(const float* __restrict__ W1, const float* __restrict__ B1,
                       const float* __restrict__ W2) {
    __shared__ float sW1[64 * 65];   // transposed [d][h], padded stride 65
    __shared__ float sBi[48 * 64];
    __shared__ float sB1[64], sW2[64];
    __shared__ float sCi[48];
    __shared__ float sMax[3], sSum[3];
    const int t = threadIdx.x, lane = t & 31, w = t >> 5;

    for (int i = t; i < 4096; i += 256) {
        int h = i >> 6, d = i & 63;
        sW1[d * 65 + h] = W1[i];      // W1 row-major [h][d] -> transposed
    }
    for (int i = t; i < 3072; i += 256) sBi[i] = g_Bi[i];
    if (t < 64) { sB1[t] = B1[t]; sW2[t] = W2[t]; }
    __syncthreads();

    for (int rr = 0; rr < 6; rr++) {
        int row = rr * 8 + w;         // row = b*3 + k, 0..47
        float c = 0.f;
#pragma unroll
        for (int hh = 0; hh < 2; hh++) {
            int hid = hh * 32 + lane;
            float a = sB1[hid];
            const float* bi = &sBi[row * 64];
#pragma unroll
            for (int dd = 0; dd < 64; dd++) a += sW1[dd * 65 + hid] * bi[dd];
            c += tanhf(a) * sW2[hid];
        }
#pragma unroll
        for (int o = 16; o; o >>= 1) c += __shfl_xor_sync(0xffffffffu, c, o);
        if (lane == 0) sCi[row] = c;
    }
    __syncthreads();
    if (t < 3) {                      // softmax over batch axis per k
        float m = -1e30f;
        for (int b = 0; b < BB; b++) m = fmaxf(m, sCi[b * 3 + t]);
        float s = 0.f;
        for (int b = 0; b < BB; b++) s += __expf(sCi[b * 3 + t] - m);
        sMax[t] = m; sSum[t] = s;
    }
    __syncthreads();
    for (int it = 0; it < 4; it++) {
        int idx = it * 256 + t;       // 0..1023 = (b, dd)
        int b = idx >> 6, dd = idx & 63;
        float o = 0.f;
#pragma unroll
        for (int k = 0; k < 3; k++) {
            float al = __expf(sCi[b * 3 + k] - sMax[k]) / sSum[k];
            o += al * sBi[(b * 3 + k) * 64 + dd];
        }
        g_CCA[idx] = o;
    }
}

// ---------------- K4: broadcast CCA_i across U ----------------
__global__ void k_bcast(float4* __restrict__ out) {
    int g = blockIdx.x * 256 + threadIdx.x;        // 524288 float4s
    int b = g >> 15;                                // 32768 float4 per batch
    int d4 = g & 15;                                // 16 float4 per row
    out[g] = *(const float4*)&g_CCA[(b * 16 + d4) * 4];
}

// ---------------- launcher ----------------
extern "C" void kernel_launch(void* const* d_in, const int* in_sizes, int n_in,
                              void* d_out, int out_size) {
    (void)in_sizes; (void)n_in; (void)out_size;
    const float* A  = (const float*)d_in[0];
    const float* V  = (const float*)d_in[1];
    const float* L  = (const float*)d_in[2];
    const float* W1 = (const float*)d_in[3];
    const float* B1 = (const float*)d_in[4];
    const float* W2 = (const float*)d_in[5];

    k_zero<<<384, 256>>>();
    k_main<<<dim3(16, 16, 3), 256>>>(A, V, L);
    k_stage2<<<dim3(3, 16), 256>>>(A, V, L);
    k_head<<<1, 256>>>(W1, B1, W2);
    k_bcast<<<2048, 256>>>((float4*)d_out);
}

// round 5
// speedup vs baseline: 1.2886x; 1.2886x over previous
#include <cuda_runtime.h>

#define U  2048
#define BB 16
#define D  32
#define ST 34          // padded SMEM row stride (floats): conflict-free LDS.64

// ---------------- device scratch (no allocations allowed) ----------------
__device__ float g_coldenom[3 * BB * U];        // Σ_i exp(s_ij) per (p,b,j)
__device__ float g_O2[3 * BB * D];              // O2[b,0,:] per (p,b)
__device__ float g_Bi[BB * 3 * 2 * D];          // Bi [b][pair][64]
__device__ __align__(16) float g_CCA[BB * 2 * D];

// ---------------- K0: zero accumulators (graph-replay safe) ----------------
__global__ void k_zero() {
    int i = blockIdx.x * blockDim.x + threadIdx.x;
    if (i < 3 * BB * U) g_coldenom[i] = 0.f;
    if (i < 3 * BB * D) g_O2[i] = 0.f;
}

// packed f32x2 helpers
__device__ __forceinline__ void fma2(unsigned long long& acc,
                                     unsigned long long a, unsigned long long b) {
    asm("fma.rn.f32x2 %0, %1, %2, %0;" : "+l"(acc) : "l"(a), "l"(b));
}
__device__ __forceinline__ float unpack_sum(unsigned long long v) {
    float lo, hi;
    asm("mov.b64 {%0,%1}, %2;" : "=f"(lo), "=f"(hi) : "l"(v));
    return lo + hi;
}

// ---------------- K1: main pass — exp row/col sums + O2 ----------------
// Tiles are i-major with padded stride ST so that (even k, odd k) pairs are
// 8-byte-contiguous: one LDS.64 yields a packed f32x2 operand.
__global__ void __launch_bounds__(256, 2)
k_main(const float* __restrict__ A, const float* __restrict__ V,
       const float* __restrict__ L) {
    const int tileI = blockIdx.x;   // 0..15  (rows i0 = tileI*128)
    const int b     = blockIdx.y;   // 0..15
    const int p     = blockIdx.z;   // 0:AV 1:AL 2:VL
    const float* f1 = (p == 2 ? V : A) + (size_t)b * U * D;
    const float* f2 = (p == 0 ? V : L) + (size_t)b * U * D;

    __shared__ float s1[128][ST];     // f1 tile, i-major (row i, 32 k + pad)
    __shared__ float s2[64][ST];      // f2 j-tile
    __shared__ float scol[16][64];    // per-ty partial column sums
    __shared__ float wbuf[128];       // exp(s_i0)/rowsum_i
    __shared__ float red[8][32];

    const int t  = threadIdx.x;
    const int tx = t & 15;            // column group: j = tx + 16*c (c 0..3)
    const int ty = t >> 4;            // row group:    i = ty + 16*r (r 0..7)

    // load f1 tile: 128 rows x 32 floats; thread -> (r = t&127, half h = t>>7)
    {
        int r = t & 127, h = t >> 7;
        const float4* src = (const float4*)(f1 + (size_t)(tileI * 128 + r) * D + h * 16);
        float4 x0 = src[0], x1 = src[1], x2 = src[2], x3 = src[3];
        unsigned long long* dst = (unsigned long long*)&s1[r][h * 16];
        dst[0] = *(unsigned long long*)&x0.x;  dst[1] = *(unsigned long long*)&x0.z;
        dst[2] = *(unsigned long long*)&x1.x;  dst[3] = *(unsigned long long*)&x1.z;
        dst[4] = *(unsigned long long*)&x2.x;  dst[5] = *(unsigned long long*)&x2.z;
        dst[6] = *(unsigned long long*)&x3.x;  dst[7] = *(unsigned long long*)&x3.z;
    }

    float rowsum[8];
    float e0[8];
#pragma unroll
    for (int r = 0; r < 8; r++) { rowsum[r] = 0.f; e0[r] = 0.f; }

    for (int jt = 0; jt < 32; ++jt) {
        __syncthreads();              // protect s2/scol from previous iter readers
        {   // load f2 j-tile: 64 rows x 32 floats; thread -> (r = t&63, q = t>>6)
            int r = t & 63, q = t >> 6;
            const float4* src = (const float4*)(f2 + (size_t)(jt * 64 + r) * D + q * 8);
            float4 x0 = src[0], x1 = src[1];
            unsigned long long* dst = (unsigned long long*)&s2[r][q * 8];
            dst[0] = *(unsigned long long*)&x0.x;  dst[1] = *(unsigned long long*)&x0.z;
            dst[2] = *(unsigned long long*)&x1.x;  dst[3] = *(unsigned long long*)&x1.z;
        }
        __syncthreads();

        unsigned long long acc2[8][4];
#pragma unroll
        for (int r = 0; r < 8; r++)
#pragma unroll
            for (int c = 0; c < 4; c++) acc2[r][c] = 0ull;

#pragma unroll
        for (int kp = 0; kp < 16; kp++) {          // k-pairs: (2kp, 2kp+1)
            unsigned long long af2[8], bf2[4];
#pragma unroll
            for (int r = 0; r < 8; r++)
                af2[r] = *(const unsigned long long*)&s1[ty + 16 * r][2 * kp];
#pragma unroll
            for (int c = 0; c < 4; c++)
                bf2[c] = *(const unsigned long long*)&s2[tx + 16 * c][2 * kp];
#pragma unroll
            for (int r = 0; r < 8; r++)
#pragma unroll
                for (int c = 0; c < 4; c++) fma2(acc2[r][c], af2[r], bf2[c]);
        }

        float cs[4];
#pragma unroll
        for (int c = 0; c < 4; c++) cs[c] = 0.f;
#pragma unroll
        for (int r = 0; r < 8; r++) {
#pragma unroll
            for (int c = 0; c < 4; c++) {
                float e = __expf(unpack_sum(acc2[r][c]));
                rowsum[r] += e;
                cs[c] += e;
            }
        }
        if (jt == 0 && tx == 0) {     // column j==0 lives at (tx=0, c=0)
#pragma unroll
            for (int r = 0; r < 8; r++) e0[r] = __expf(unpack_sum(acc2[r][0]));
        }
#pragma unroll
        for (int c = 0; c < 4; c++) scol[ty][tx + 16 * c] = cs[c];
        __syncthreads();
        if (t < 64) {
            float s = 0.f;
#pragma unroll
            for (int y = 0; y < 16; y++) s += scol[y][t];
            atomicAdd(&g_coldenom[(p * BB + b) * U + jt * 64 + t], s);
        }
    }

    // row denominators: reduce across the 16 tx lanes (same half-warp)
#pragma unroll
    for (int r = 0; r < 8; r++) {
        float s = rowsum[r];
#pragma unroll
        for (int o = 8; o; o >>= 1) s += __shfl_xor_sync(0xffffffffu, s, o, 16);
        if (tx == 0) wbuf[ty + 16 * r] = e0[r] / s;
    }
    __syncthreads();

    // partial O2[d] = Σ_i w_i * f1[i][d]   (s1 is [i][d])
    {
        int d = t & 31, ch = t >> 5;
        float po = 0.f;
#pragma unroll
        for (int ii = 0; ii < 16; ii++) {
            int i = ch * 16 + ii;
            po += wbuf[i] * s1[i][d];
        }
        red[ch][d] = po;
    }
    __syncthreads();
    if (t < 32) {
        float s = 0.f;
#pragma unroll
        for (int ch = 0; ch < 8; ch++) s += red[ch][t];
        atomicAdd(&g_O2[(p * BB + b) * D + t], s);
    }
}

// ---------------- K2: finish O1, build Bi (thread-per-j, no shfl chains) ----
__global__ void k_stage2(const float* __restrict__ A, const float* __restrict__ V,
                         const float* __restrict__ L) {
    const int p = blockIdx.x, b = blockIdx.y;
    const float* f1 = (p == 2 ? V : A) + (size_t)b * U * D;
    const float* f2 = (p == 0 ? V : L) + (size_t)b * U * D;
    const int t = threadIdx.x;
    __shared__ float sF10[32];
    __shared__ float sAcc[256][33];   // padded: conflict-free column reads
    __shared__ float red[8][32];

    if (t < 32) sF10[t] = f1[t];
    __syncthreads();

    float acc[32];
#pragma unroll
    for (int d = 0; d < 32; d++) acc[d] = 0.f;

    const float* cd = &g_coldenom[(p * BB + b) * U];
    for (int it = 0; it < 8; it++) {
        int j = it * 256 + t;
        float f[32];
        const float4* row = (const float4*)(f2 + (size_t)j * D);
#pragma unroll
        for (int q = 0; q < 8; q++) *(float4*)&f[q * 4] = row[q];
        float dot = 0.f;
#pragma unroll
        for (int k = 0; k < 32; k++) dot += f[k] * sF10[k];
        float w = __expf(dot) / cd[j];
#pragma unroll
        for (int d = 0; d < 32; d++) acc[d] += w * f[d];
    }
#pragma unroll
    for (int d = 0; d < 32; d++) sAcc[t][d] = acc[d];
    __syncthreads();
    {
        int d = t & 31, g = t >> 5;
        float s = 0.f;
#pragma unroll
        for (int m = 0; m < 32; m++) s += sAcc[g * 32 + m][d];
        red[g][d] = s;
    }
    __syncthreads();
    if (t < 32) {
        float o1 = 0.f;
#pragma unroll
        for (int g = 0; g < 8; g++) o1 += red[g][t];
        float f10 = sF10[t];
        float f20 = f2[t];
        g_Bi[b * 192 + p * 64 + t]      = o1 * f10;                         // A1[b,0,:]
        g_Bi[b * 192 + p * 64 + 32 + t] = g_O2[(p * BB + b) * D + t] * f20; // A2[b,0,:]
    }
}

// ---------------- K3: FC head + batch softmax + CCA ----------------
__device__ __forceinline__ float fast_tanh(float x) {
    float y;
    asm("tanh.approx.f32 %0, %1;" : "=f"(y) : "f"(x));
    return y;
}

__global__ void k_head(const float* __restrict__ W1, const float* __restrict__ B1,
                       const float* __restrict__ W2) {
    __shared__ float sW1[64 * 65];   // transposed [d][h], padded stride 65
    __shared__ float sBi[48 * 64];
    __shared__ float sB1[64], sW2[64];
    __shared__ float sCi[48];
    __shared__ float sMax[3], sSum[3];
    const int t = threadIdx.x, lane = t & 31, w = t >> 5;

    for (int i = t; i < 4096; i += 256) {
        int h = i >> 6, d = i & 63;
        sW1[d * 65 + h] = W1[i];      // W1 row-major [h][d] -> transposed
    }
    for (int i = t; i < 3072; i += 256) sBi[i] = g_Bi[i];
    if (t < 64) { sB1[t] = B1[t]; sW2[t] = W2[t]; }
    __syncthreads();

    for (int rr = 0; rr < 6; rr++) {
        int row = rr * 8 + w;         // row = b*3 + k, 0..47
        float c = 0.f;
#pragma unroll
        for (int hh = 0; hh < 2; hh++) {
            int hid = hh * 32 + lane;
            float a = sB1[hid];
            const float* bi = &sBi[row * 64];
#pragma unroll
            for (int dd = 0; dd < 64; dd++) a += sW1[dd * 65 + hid] * bi[dd];
            c += fast_tanh(a) * sW2[hid];
        }
#pragma unroll
        for (int o = 16; o; o >>= 1) c += __shfl_xor_sync(0xffffffffu, c, o);
        if (lane == 0) sCi[row] = c;
    }
    __syncthreads();
    if (t < 3) {                      // softmax over batch axis per k
        float m = -1e30f;
        for (int b = 0; b < BB; b++) m = fmaxf(m, sCi[b * 3 + t]);
        float s = 0.f;
        for (int b = 0; b < BB; b++) s += __expf(sCi[b * 3 + t] - m);
        sMax[t] = m; sSum[t] = s;
    }
    __syncthreads();
    for (int it = 0; it < 4; it++) {
        int idx = it * 256 + t;       // 0..1023 = (b, dd)
        int b = idx >> 6, dd = idx & 63;
        float o = 0.f;
#pragma unroll
        for (int k = 0; k < 3; k++) {
            float al = __expf(sCi[b * 3 + k] - sMax[k]) / sSum[k];
            o += al * sBi[(b * 3 + k) * 64 + dd];
        }
        g_CCA[idx] = o;
    }
}

// ---------------- K4: broadcast CCA_i across U ----------------
__global__ void k_bcast(float4* __restrict__ out) {
    int g = blockIdx.x * 256 + threadIdx.x;        // 524288 float4s
    int b = g >> 15;                                // 32768 float4 per batch
    int d4 = g & 15;                                // 16 float4 per row
    out[g] = *(const float4*)&g_CCA[(b * 16 + d4) * 4];
}

// ---------------- launcher ----------------
extern "C" void kernel_launch(void* const* d_in, const int* in_sizes, int n_in,
                              void* d_out, int out_size) {
    (void)in_sizes; (void)n_in; (void)out_size;
    const float* A  = (const float*)d_in[0];
    const float* V  = (const float*)d_in[1];
    const float* L  = (const float*)d_in[2];
    const float* W1 = (const float*)d_in[3];
    const float* B1 = (const float*)d_in[4];
    const float* W2 = (const float*)d_in[5];

    k_zero<<<384, 256>>>();
    k_main<<<dim3(16, 16, 3), 256>>>(A, V, L);
    k_stage2<<<dim3(3, 16), 256>>>(A, V, L);
    k_head<<<1, 256>>>(W1, B1, W2);
    k_bcast<<<2048, 256>>>((float4*)d_out);
}

// round 7
// speedup vs baseline: 1.9634x; 1.5237x over previous
#include <cuda_runtime.h>
#include <cuda_bf16.h>
#include <cstdint>

#define U  2048
#define BB 16
#define D  32

// ---------------- device scratch (no allocations allowed) ----------------
__device__ float g_coldenom[3 * BB * U];          // Σ_i exp(s_ij) per (p,b,j)
__device__ float g_O2[3 * BB * D];                // O2[b,0,:] per (p,b)
__device__ float g_Bi[BB * 3 * 2 * D];            // Bi [b][pair][64]
__device__ __align__(16) float g_CCA[BB * 2 * D];
// packed bf16-split inputs: per modality [B,U,64] = [hi(32) | lo(32)] per row
__device__ __align__(16) __nv_bfloat16 g_pack[3][BB * U * 64];

// ---------------- helpers ----------------
__device__ __forceinline__ uint32_t smem_u32(const void* p) {
    uint32_t a;
    asm("{ .reg .u64 t; cvta.to.shared.u64 t, %1; cvt.u32.u64 %0, t; }" : "=r"(a) : "l"(p));
    return a;
}
__device__ __forceinline__ void ldsm4(uint32_t* r, uint32_t addr) {
    asm volatile("ldmatrix.sync.aligned.m8n8.x4.shared.b16 {%0,%1,%2,%3}, [%4];"
                 : "=r"(r[0]), "=r"(r[1]), "=r"(r[2]), "=r"(r[3]) : "r"(addr));
}
__device__ __forceinline__ void mma_bf16(float* c, const uint32_t* a,
                                         uint32_t b0, uint32_t b1) {
    asm volatile(
        "mma.sync.aligned.m16n8k16.row.col.f32.bf16.bf16.f32 "
        "{%0,%1,%2,%3}, {%4,%5,%6,%7}, {%8,%9}, {%0,%1,%2,%3};"
        : "+f"(c[0]), "+f"(c[1]), "+f"(c[2]), "+f"(c[3])
        : "r"(a[0]), "r"(a[1]), "r"(a[2]), "r"(a[3]), "r"(b0), "r"(b1));
}

#define RSTRIDE 72   // SMEM row stride in bf16 (144 B) — conflict-free ldmatrix

// ---------------- K0: zero accumulators ----------------
__global__ void k_zero() {
    int i = blockIdx.x * blockDim.x + threadIdx.x;
    if (i < 3 * BB * U) g_coldenom[i] = 0.f;
    if (i < 3 * BB * D) g_O2[i] = 0.f;
}

// ---------------- Kp: pack fp32 -> bf16 split [hi|lo] ----------------
__global__ void k_pack(const float* __restrict__ A, const float* __restrict__ V,
                       const float* __restrict__ L) {
    int m = blockIdx.y;
    const float* src = (m == 0 ? A : (m == 1 ? V : L));
    int t = blockIdx.x * 256 + threadIdx.x;           // 0 .. 1048575
    float x = src[t];
    __nv_bfloat16 hi = __float2bfloat16(x);
    __nv_bfloat16 lo = __float2bfloat16(x - __bfloat162float(hi));
    int row = t >> 5, k = t & 31;
    g_pack[m][(size_t)row * 64 + k]      = hi;
    g_pack[m][(size_t)row * 64 + 32 + k] = lo;
}

// ---------------- K1: HMMA main pass ----------------
__global__ void __launch_bounds__(256, 1)
k_main() {
    __shared__ __nv_bfloat16 s1[128 * RSTRIDE];       // f1 i-tile
    __shared__ __nv_bfloat16 s2[128 * RSTRIDE];       // f2 j-tile
    __shared__ float srow[128];                       // Σ_j exp(s_ij), this i-tile
    __shared__ float se0[128];                        // exp(s_i0)
    __shared__ float wbuf[128];
    __shared__ float red[8][32];

    const int tileI = blockIdx.x, b = blockIdx.y, p = blockIdx.z;
    const int m1 = (p == 2) ? 1 : 0;                  // f1: A,A,V
    const int m2 = (p == 0) ? 1 : 2;                  // f2: V,L,L
    const __nv_bfloat16* F1 = &g_pack[m1][(size_t)(b * U + tileI * 128) * 64];
    const __nv_bfloat16* F2 = &g_pack[m2][(size_t)b * U * 64];

    const int t = threadIdx.x;
    const int wid = t >> 5, lane = t & 31;
    const int warp_m = wid & 1;                       // 0/1 -> rows 0-63 / 64-127
    const int warp_n = wid >> 1;                      // 0..3 -> 32-col slabs

    if (t < 128) { srow[t] = 0.f; se0[t] = 0.f; }

    // load f1 tile: 128 rows x 128B, row stride 144B
#pragma unroll
    for (int q = 0; q < 4; q++) {
        int lin = q * 256 + t;                        // 16B units
        uint4 v = ((const uint4*)F1)[lin];
        *(uint4*)((char*)s1 + (lin >> 3) * 144 + (lin & 7) * 16) = v;
    }
#pragma unroll
    for (int q = 0; q < 4; q++) {
        int lin = q * 256 + t;
        uint4 v = ((const uint4*)F2)[lin];
        *(uint4*)((char*)s2 + (lin >> 3) * 144 + (lin & 7) * 16) = v;
    }
    __syncthreads();

    const uint32_t s1b = smem_u32(s1), s2b = smem_u32(s2);
    // bf16-split products hi*hi + hi*lo + lo*hi, k16 chunks (element offsets)
    const int AK[6] = {0, 16, 0, 16, 32, 48};
    const int BK[6] = {0, 16, 32, 48, 0, 16};

    const uint32_t a_rowoff = (uint32_t)(warp_m * 64 + (lane & 15)) * 144;
    const uint32_t a_koff   = (uint32_t)(lane >> 4) * 16;          // 8 elems = 16B
    const uint32_t b_rowoff = (uint32_t)(warp_n * 32 + ((lane >> 4) << 3) + (lane & 7)) * 144;
    const uint32_t b_koff   = (uint32_t)((lane >> 3) & 1) * 16;

    const int cdbase = (p * BB + b) * U;

    for (int jt = 0; jt < 16; ++jt) {
        // prefetch next j-tile into registers (overlaps MMA)
        uint4 pf[4];
        if (jt + 1 < 16) {
            const uint4* src = (const uint4*)(F2 + (size_t)(jt + 1) * 128 * 64);
#pragma unroll
            for (int q = 0; q < 4; q++) pf[q] = src[q * 256 + t];
        }

        float acc[4][4][4];
#pragma unroll
        for (int ma = 0; ma < 4; ma++)
#pragma unroll
            for (int na = 0; na < 4; na++)
#pragma unroll
                for (int k = 0; k < 4; k++) acc[ma][na][k] = 0.f;

#pragma unroll
        for (int s = 0; s < 6; s++) {
            uint32_t afr[4][4];
#pragma unroll
            for (int ma = 0; ma < 4; ma++)
                ldsm4(afr[ma], s1b + a_rowoff + (uint32_t)ma * 16 * 144 +
                               (uint32_t)AK[s] * 2 + a_koff);
            uint32_t bfr[2][4];
#pragma unroll
            for (int q = 0; q < 2; q++)
                ldsm4(bfr[q], s2b + b_rowoff + (uint32_t)q * 16 * 144 +
                              (uint32_t)BK[s] * 2 + b_koff);
#pragma unroll
            for (int ma = 0; ma < 4; ma++)
#pragma unroll
                for (int na = 0; na < 4; na++)
                    mma_bf16(acc[ma][na], afr[ma],
                             bfr[na >> 1][(na & 1) * 2], bfr[na >> 1][(na & 1) * 2 + 1]);
        }

        // epilogue: exp + row/col reductions in registers
        float colp[4][2];
#pragma unroll
        for (int na = 0; na < 4; na++) { colp[na][0] = 0.f; colp[na][1] = 0.f; }

#pragma unroll
        for (int ma = 0; ma < 4; ma++) {
            float rp0 = 0.f, rp1 = 0.f;
#pragma unroll
            for (int na = 0; na < 4; na++) {
                float v0 = __expf(acc[ma][na][0]);
                float v1 = __expf(acc[ma][na][1]);
                float v2 = __expf(acc[ma][na][2]);
                float v3 = __expf(acc[ma][na][3]);
                rp0 += v0 + v1;  rp1 += v2 + v3;
                colp[na][0] += v0 + v2;  colp[na][1] += v1 + v3;
                if (jt == 0 && warp_n == 0 && na == 0 && (lane & 3) == 0) {
                    int r0 = warp_m * 64 + ma * 16 + (lane >> 2);
                    se0[r0]     = v0;                 // col 0, row r0
                    se0[r0 + 8] = v2;                 // col 0, row r0+8
                }
            }
            rp0 += __shfl_xor_sync(0xffffffffu, rp0, 1);
            rp0 += __shfl_xor_sync(0xffffffffu, rp0, 2);
            rp1 += __shfl_xor_sync(0xffffffffu, rp1, 1);
            rp1 += __shfl_xor_sync(0xffffffffu, rp1, 2);
            if ((lane & 3) == 0) {
                int r0 = warp_m * 64 + ma * 16 + (lane >> 2);
                atomicAdd(&srow[r0], rp0);
                atomicAdd(&srow[r0 + 8], rp1);
            }
        }
#pragma unroll
        for (int na = 0; na < 4; na++) {
#pragma unroll
            for (int par = 0; par < 2; par++) {
                float c = colp[na][par];
                c += __shfl_xor_sync(0xffffffffu, c, 4);
                c += __shfl_xor_sync(0xffffffffu, c, 8);
                c += __shfl_xor_sync(0xffffffffu, c, 16);
                if ((lane >> 2) == 0)                 // lanes 0..3
                    atomicAdd(&g_coldenom[cdbase + jt * 128 + warp_n * 32 +
                                          na * 8 + 2 * lane + par], c);
            }
        }

        __syncthreads();                              // all ldmatrix reads done
        if (jt + 1 < 16) {
#pragma unroll
            for (int q = 0; q < 4; q++) {
                int lin = q * 256 + t;
                *(uint4*)((char*)s2 + (lin >> 3) * 144 + (lin & 7) * 16) = pf[q];
            }
        }
        __syncthreads();
    }

    if (t < 128) wbuf[t] = se0[t] / srow[t];
    __syncthreads();

    // O2 partial: Σ_i w_i * f1[i][d]   (f1 = hi + lo from s1)
    {
        int d = t & 31, chk = t >> 5;
        float po = 0.f;
#pragma unroll
        for (int ii = 0; ii < 16; ii++) {
            int i = chk * 16 + ii;
            float f = __bfloat162float(s1[i * RSTRIDE + d]) +
                      __bfloat162float(s1[i * RSTRIDE + 32 + d]);
            po += wbuf[i] * f;
        }
        red[chk][d] = po;
    }
    __syncthreads();
    if (t < 32) {
        float s = 0.f;
#pragma unroll
        for (int c = 0; c < 8; c++) s += red[c][t];
        atomicAdd(&g_O2[(p * BB + b) * D + t], s);
    }
}

// ---------------- K2: finish O1, build Bi ----------------
__global__ void k_stage2(const float* __restrict__ A, const float* __restrict__ V,
                         const float* __restrict__ L) {
    const int p = blockIdx.x, b = blockIdx.y;
    const float* f1 = (p == 2 ? V : A) + (size_t)b * U * D;
    const float* f2 = (p == 0 ? V : L) + (size_t)b * U * D;
    const int t = threadIdx.x;
    __shared__ float sF10[32];
    __shared__ float sAcc[256][33];
    __shared__ float red[8][32];

    if (t < 32) sF10[t] = f1[t];
    __syncthreads();

    float acc[32];
#pragma unroll
    for (int d = 0; d < 32; d++) acc[d] = 0.f;

    const float* cd = &g_coldenom[(p * BB + b) * U];
    for (int it = 0; it < 8; it++) {
        int j = it * 256 + t;
        float f[32];
        const float4* rowp = (const float4*)(f2 + (size_t)j * D);
#pragma unroll
        for (int q = 0; q < 8; q++) *(float4*)&f[q * 4] = rowp[q];
        float dot = 0.f;
#pragma unroll
        for (int k = 0; k < 32; k++) dot += f[k] * sF10[k];
        float w = __expf(dot) / cd[j];
#pragma unroll
        for (int d = 0; d < 32; d++) acc[d] += w * f[d];
    }
#pragma unroll
    for (int d = 0; d < 32; d++) sAcc[t][d] = acc[d];
    __syncthreads();
    {
        int d = t & 31, g = t >> 5;
        float s = 0.f;
#pragma unroll
        for (int m = 0; m < 32; m++) s += sAcc[g * 32 + m][d];
        red[g][d] = s;
    }
    __syncthreads();
    if (t < 32) {
        float o1 = 0.f;
#pragma unroll
        for (int g = 0; g < 8; g++) o1 += red[g][t];
        g_Bi[b * 192 + p * 64 + t]      = o1 * sF10[t];
        g_Bi[b * 192 + p * 64 + 32 + t] = g_O2[(p * BB + b) * D + t] * f2[t];
    }
}

// ---------------- K3: FC head + batch softmax + CCA ----------------
__device__ __forceinline__ float fast_tanh(float x) {
    float y;
    asm("tanh.approx.f32 %0, %1;" : "=f"(y) : "f"(x));
    return y;
}

__global__ void k_head(const float* __restrict__ W1, const float* __restrict__ B1,
                       const float* __restrict__ W2) {
    __shared__ float sW1[64 * 65];
    __shared__ float sBi[48 * 64];
    __shared__ float sB1[64], sW2[64];
    __shared__ float sCi[48];
    __shared__ float sMax[3], sSum[3];
    const int t = threadIdx.x, lane = t & 31, w = t >> 5;

    for (int i = t; i < 4096; i += 256) {
        int h = i >> 6, d = i & 63;
        sW1[d * 65 + h] = W1[i];
    }
    for (int i = t; i < 3072; i += 256) sBi[i] = g_Bi[i];
    if (t < 64) { sB1[t] = B1[t]; sW2[t] = W2[t]; }
    __syncthreads();

    for (int rr = 0; rr < 6; rr++) {
        int row = rr * 8 + w;
        float c = 0.f;
#pragma unroll
        for (int hh = 0; hh < 2; hh++) {
            int hid = hh * 32 + lane;
            float a = sB1[hid];
            const float* bi = &sBi[row * 64];
#pragma unroll
            for (int dd = 0; dd < 64; dd++) a += sW1[dd * 65 + hid] * bi[dd];
            c += fast_tanh(a) * sW2[hid];
        }
#pragma unroll
        for (int o = 16; o; o >>= 1) c += __shfl_xor_sync(0xffffffffu, c, o);
        if (lane == 0) sCi[row] = c;
    }
    __syncthreads();
    if (t < 3) {
        float m = -1e30f;
        for (int b = 0; b < BB; b++) m = fmaxf(m, sCi[b * 3 + t]);
        float s = 0.f;
        for (int b = 0; b < BB; b++) s += __expf(sCi[b * 3 + t] - m);
        sMax[t] = m; sSum[t] = s;
    }
    __syncthreads();
    for (int it = 0; it < 4; it++) {
        int idx = it * 256 + t;
        int b = idx >> 6, dd = idx & 63;
        float o = 0.f;
#pragma unroll
        for (int k = 0; k < 3; k++) {
            float al = __expf(sCi[b * 3 + k] - sMax[k]) / sSum[k];
            o += al * sBi[(b * 3 + k) * 64 + dd];
        }
        g_CCA[idx] = o;
    }
}

// ---------------- K4: broadcast CCA_i across U ----------------
__global__ void k_bcast(float4* __restrict__ out) {
    int g = blockIdx.x * 256 + threadIdx.x;
    int b = g >> 15;
    int d4 = g & 15;
    out[g] = *(const float4*)&g_CCA[(b * 16 + d4) * 4];
}

// ---------------- launcher ----------------
extern "C" void kernel_launch(void* const* d_in, const int* in_sizes, int n_in,
                              void* d_out, int out_size) {
    (void)in_sizes; (void)n_in; (void)out_size;
    const float* A  = (const float*)d_in[0];
    const float* V  = (const float*)d_in[1];
    const float* L  = (const float*)d_in[2];
    const float* W1 = (const float*)d_in[3];
    const float* B1 = (const float*)d_in[4];
    const float* W2 = (const float*)d_in[5];

    k_zero<<<384, 256>>>();
    k_pack<<<dim3(4096, 3), 256>>>(A, V, L);
    k_main<<<dim3(16, 16, 3), 256>>>();
    k_stage2<<<dim3(3, 16), 256>>>(A, V, L);
    k_head<<<1, 256>>>(W1, B1, W2);
    k_bcast<<<2048, 256>>>((float4*)d_out);
}

// round 8
// speedup vs baseline: 2.7190x; 1.3848x over previous
#include <cuda_runtime.h>
#include <cuda_bf16.h>
#include <cstdint>

#define U  2048
#define BB 16
#define D  32
#define LOG2E 1.4426950408889634f
#define LN2   0.6931471805599453f

// ---------------- device scratch (no allocations allowed) ----------------
__device__ float g_coldenom[3 * BB * U];          // Σ_i exp(s_ij) per (p,b,j)
__device__ float g_O2[3 * BB * D];                // O2[b,0,:] per (p,b)
__device__ float g_O1[3 * BB * D];                // O1[b,0,:] partial sums
__device__ __align__(16) float g_CCA[BB * 2 * D];
// packed bf16-split: 0=A*log2e, 1=V, 2=L, 3=V*log2e ; [B,U,64]=[hi|lo] rows
__device__ __align__(16) __nv_bfloat16 g_pack[4][BB * U * 64];

// ---------------- helpers ----------------
__device__ __forceinline__ uint32_t smem_u32(const void* p) {
    uint32_t a;
    asm("{ .reg .u64 t; cvta.to.shared.u64 t, %1; cvt.u32.u64 %0, t; }" : "=r"(a) : "l"(p));
    return a;
}
__device__ __forceinline__ void ldsm4(uint32_t* r, uint32_t addr) {
    asm volatile("ldmatrix.sync.aligned.m8n8.x4.shared.b16 {%0,%1,%2,%3}, [%4];"
                 : "=r"(r[0]), "=r"(r[1]), "=r"(r[2]), "=r"(r[3]) : "r"(addr));
}
__device__ __forceinline__ void mma_bf16(float* c, const uint32_t* a,
                                         uint32_t b0, uint32_t b1) {
    asm volatile(
        "mma.sync.aligned.m16n8k16.row.col.f32.bf16.bf16.f32 "
        "{%0,%1,%2,%3}, {%4,%5,%6,%7}, {%8,%9}, {%0,%1,%2,%3};"
        : "+f"(c[0]), "+f"(c[1]), "+f"(c[2]), "+f"(c[3])
        : "r"(a[0]), "r"(a[1]), "r"(a[2]), "r"(a[3]), "r"(b0), "r"(b1));
}
__device__ __forceinline__ float ex2(float x) {
    float y; asm("ex2.approx.f32 %0, %1;" : "=f"(y) : "f"(x)); return y;
}
__device__ __forceinline__ void cp16(uint32_t dst, const void* src) {
    asm volatile("cp.async.cg.shared.global [%0], [%1], 16;" :: "r"(dst), "l"(src));
}
#define CP_COMMIT() asm volatile("cp.async.commit_group;" ::: "memory")
#define CP_WAIT0()  asm volatile("cp.async.wait_group 0;" ::: "memory")

#define RSTRIDE 72            // SMEM row stride in bf16 (144 B)
#define TILE_B  (128 * 144)   // 18432 B per tile
// dynamic smem layout: s1 | s2[0] | s2[1] | floats
#define SM_S1 0
#define SM_S2 TILE_B
#define SM_F  (3 * TILE_B)
#define SMEM_TOTAL (SM_F + (128 * 3 + 8 * 32) * 4)

// ---------------- K0: zero accumulators ----------------
__global__ void k_zero() {
    int i = blockIdx.x * blockDim.x + threadIdx.x;
    if (i < 3 * BB * U) g_coldenom[i] = 0.f;
    if (i < 3 * BB * D) { g_O2[i] = 0.f; g_O1[i] = 0.f; }
}

// ---------------- Kp: pack fp32 -> bf16 split [hi|lo] (x log2e one side) ----
__global__ void k_pack(const float* __restrict__ A, const float* __restrict__ V,
                       const float* __restrict__ L) {
    int m = blockIdx.y;                               // 0:A*s 1:V 2:L 3:V*s
    const float* src = (m == 0) ? A : (m == 2 ? L : V);
    float scale = (m == 0 || m == 3) ? LOG2E : 1.f;
    int t = blockIdx.x * 256 + threadIdx.x;           // 0 .. 1048575
    float x = src[t] * scale;
    __nv_bfloat16 hi = __float2bfloat16(x);
    __nv_bfloat16 lo = __float2bfloat16(x - __bfloat162float(hi));
    int row = t >> 5, k = t & 31;
    g_pack[m][(size_t)row * 64 + k]      = hi;
    g_pack[m][(size_t)row * 64 + 32 + k] = lo;
}

// ---------------- K1: HMMA main pass (2 CTAs/SM, cp.async double buffer) ----
__global__ void __launch_bounds__(256, 2)
k_main() {
    extern __shared__ char smem[];
    float* srow = (float*)(smem + SM_F);              // [128]
    float* se0  = srow + 128;                         // [128]
    float* wbuf = se0 + 128;                          // [128]
    float (*red)[32] = (float (*)[32])(wbuf + 128);   // [8][32]

    const int tileI = blockIdx.x, b = blockIdx.y, p = blockIdx.z;
    const int m1 = (p == 2) ? 3 : 0;                  // f1 (scaled): A,A,V
    const int m2 = (p == 0) ? 1 : 2;                  // f2: V,L,L
    const __nv_bfloat16* F1 = &g_pack[m1][(size_t)(b * U + tileI * 128) * 64];
    const __nv_bfloat16* F2 = &g_pack[m2][(size_t)b * U * 64];

    const int t = threadIdx.x;
    const int wid = t >> 5, lane = t & 31;
    const int warp_m = wid & 1;
    const int warp_n = wid >> 1;

    const uint32_t sb = smem_u32(smem);
    const uint32_t s1b = sb + SM_S1;
    const uint32_t s2b = sb + SM_S2;

    if (t < 128) { srow[t] = 0.f; se0[t] = 0.f; }

    // prologue: async-load f1 tile and first f2 tile
#pragma unroll
    for (int q = 0; q < 4; q++) {
        int lin = q * 256 + t;                        // 16B units
        uint32_t so = (uint32_t)(lin >> 3) * 144 + (uint32_t)(lin & 7) * 16;
        cp16(s1b + so, (const uint4*)F1 + lin);
        cp16(s2b + so, (const uint4*)F2 + lin);
    }
    CP_COMMIT();
    CP_WAIT0();
    __syncthreads();

    const int AK[6] = {0, 16, 0, 16, 32, 48};
    const int BK[6] = {0, 16, 32, 48, 0, 16};

    const uint32_t a_rowoff = (uint32_t)(warp_m * 64 + (lane & 15)) * 144;
    const uint32_t a_koff   = (uint32_t)(lane >> 4) * 16;
    const uint32_t b_rowoff = (uint32_t)(warp_n * 32 + ((lane >> 4) << 3) + (lane & 7)) * 144;
    const uint32_t b_koff   = (uint32_t)((lane >> 3) & 1) * 16;
    const int cdbase = (p * BB + b) * U;

    for (int jt = 0; jt < 16; ++jt) {
        const uint32_t cur = (uint32_t)(jt & 1) * TILE_B;
        if (jt + 1 < 16) {                            // prefetch next j-tile
            const uint4* src = (const uint4*)(F2 + (size_t)(jt + 1) * 128 * 64);
            const uint32_t dst = s2b + (TILE_B - cur);
#pragma unroll
            for (int q = 0; q < 4; q++) {
                int lin = q * 256 + t;
                cp16(dst + (uint32_t)(lin >> 3) * 144 + (uint32_t)(lin & 7) * 16,
                     src + lin);
            }
            CP_COMMIT();
        }

        float acc[4][4][4];
#pragma unroll
        for (int ma = 0; ma < 4; ma++)
#pragma unroll
            for (int na = 0; na < 4; na++)
#pragma unroll
                for (int k = 0; k < 4; k++) acc[ma][na][k] = 0.f;

#pragma unroll
        for (int s = 0; s < 6; s++) {
            uint32_t afr[4][4];
#pragma unroll
            for (int ma = 0; ma < 4; ma++)
                ldsm4(afr[ma], s1b + a_rowoff + (uint32_t)ma * 16 * 144 +
                               (uint32_t)AK[s] * 2 + a_koff);
            uint32_t bfr[2][4];
#pragma unroll
            for (int q = 0; q < 2; q++)
                ldsm4(bfr[q], s2b + cur + b_rowoff + (uint32_t)q * 16 * 144 +
                              (uint32_t)BK[s] * 2 + b_koff);
#pragma unroll
            for (int ma = 0; ma < 4; ma++)
#pragma unroll
                for (int na = 0; na < 4; na++)
                    mma_bf16(acc[ma][na], afr[ma],
                             bfr[na >> 1][(na & 1) * 2], bfr[na >> 1][(na & 1) * 2 + 1]);
        }

        // epilogue: exp2 + row/col reductions (logits pre-scaled by log2e)
        float colp[4][2];
#pragma unroll
        for (int na = 0; na < 4; na++) { colp[na][0] = 0.f; colp[na][1] = 0.f; }

#pragma unroll
        for (int ma = 0; ma < 4; ma++) {
            float rp0 = 0.f, rp1 = 0.f;
#pragma unroll
            for (int na = 0; na < 4; na++) {
                float v0 = ex2(acc[ma][na][0]);
                float v1 = ex2(acc[ma][na][1]);
                float v2 = ex2(acc[ma][na][2]);
                float v3 = ex2(acc[ma][na][3]);
                rp0 += v0 + v1;  rp1 += v2 + v3;
                colp[na][0] += v0 + v2;  colp[na][1] += v1 + v3;
                if (jt == 0 && warp_n == 0 && na == 0 && (lane & 3) == 0) {
                    int r0 = warp_m * 64 + ma * 16 + (lane >> 2);
                    se0[r0]     = v0;
                    se0[r0 + 8] = v2;
                }
            }
            rp0 += __shfl_xor_sync(0xffffffffu, rp0, 1);
            rp0 += __shfl_xor_sync(0xffffffffu, rp0, 2);
            rp1 += __shfl_xor_sync(0xffffffffu, rp1, 1);
            rp1 += __shfl_xor_sync(0xffffffffu, rp1, 2);
            if ((lane & 3) == 0) {
                int r0 = warp_m * 64 + ma * 16 + (lane >> 2);
                atomicAdd(&srow[r0], rp0);
                atomicAdd(&srow[r0 + 8], rp1);
            }
        }
#pragma unroll
        for (int na = 0; na < 4; na++) {
#pragma unroll
            for (int par = 0; par < 2; par++) {
                float c = colp[na][par];
                c += __shfl_xor_sync(0xffffffffu, c, 4);
                c += __shfl_xor_sync(0xffffffffu, c, 8);
                c += __shfl_xor_sync(0xffffffffu, c, 16);
                if ((lane >> 2) == 0)
                    atomicAdd(&g_coldenom[cdbase + jt * 128 + warp_n * 32 +
                                          na * 8 + 2 * lane + par], c);
            }
        }

        CP_WAIT0();                                   // next j-tile landed
        __syncthreads();
    }

    if (t < 128) wbuf[t] = se0[t] / srow[t];
    __syncthreads();

    // O2 partial: Σ_i w_i * f1[i][d]  (s1 holds log2e-scaled f1 -> fix with LN2)
    {
        int d = t & 31, chk = t >> 5;
        const __nv_bfloat16* s1h = (const __nv_bfloat16*)smem;
        float po = 0.f;
#pragma unroll
        for (int ii = 0; ii < 16; ii++) {
            int i = chk * 16 + ii;
            float f = __bfloat162float(s1h[i * RSTRIDE + d]) +
                      __bfloat162float(s1h[i * RSTRIDE + 32 + d]);
            po += wbuf[i] * f;
        }
        red[chk][d] = po;
    }
    __syncthreads();
    if (t < 32) {
        float s = 0.f;
#pragma unroll
        for (int c = 0; c < 8; c++) s += red[c][t];
        atomicAdd(&g_O2[(p * BB + b) * D + t], s * LN2);
    }
}

// ---------------- K2: O1 partial sums (split 4x over j) ----------------
__global__ void k_stage2(const float* __restrict__ A, const float* __restrict__ V,
                         const float* __restrict__ L) {
    const int p = blockIdx.x, b = blockIdx.y, z = blockIdx.z;
    const float* f1 = (p == 2 ? V : A) + (size_t)b * U * D;
    const float* f2 = (p == 0 ? V : L) + (size_t)b * U * D;
    const int t = threadIdx.x;
    __shared__ float sF10[32];
    __shared__ float sAcc[256][33];
    __shared__ float red[8][32];

    if (t < 32) sF10[t] = f1[t];
    __syncthreads();

    float acc[32];
#pragma unroll
    for (int d = 0; d < 32; d++) acc[d] = 0.f;

    const float* cd = &g_coldenom[(p * BB + b) * U];
    for (int it = 0; it < 2; it++) {
        int j = z * 512 + it * 256 + t;
        float f[32];
        const float4* rowp = (const float4*)(f2 + (size_t)j * D);
#pragma unroll
        for (int q = 0; q < 8; q++) *(float4*)&f[q * 4] = rowp[q];
        float dot = 0.f;
#pragma unroll
        for (int k = 0; k < 32; k++) dot += f[k] * sF10[k];
        float w = __expf(dot) / cd[j];
#pragma unroll
        for (int d = 0; d < 32; d++) acc[d] += w * f[d];
    }
#pragma unroll
    for (int d = 0; d < 32; d++) sAcc[t][d] = acc[d];
    __syncthreads();
    {
        int d = t & 31, g = t >> 5;
        float s = 0.f;
#pragma unroll
        for (int m = 0; m < 32; m++) s += sAcc[g * 32 + m][d];
        red[g][d] = s;
    }
    __syncthreads();
    if (t < 32) {
        float o1 = 0.f;
#pragma unroll
        for (int g = 0; g < 8; g++) o1 += red[g][t];
        atomicAdd(&g_O1[(p * BB + b) * D + t], o1);
    }
}

// ---------------- K3: Bi assembly + FC head + batch softmax + CCA ----------
__device__ __forceinline__ float fast_tanh(float x) {
    float y;
    asm("tanh.approx.f32 %0, %1;" : "=f"(y) : "f"(x));
    return y;
}

__global__ void k_head(const float* __restrict__ W1, const float* __restrict__ B1,
                       const float* __restrict__ W2, const float* __restrict__ A,
                       const float* __restrict__ V, const float* __restrict__ L) {
    __shared__ float sW1[64 * 65];
    __shared__ float sBi[48 * 64];
    __shared__ float sB1[64], sW2[64];
    __shared__ float sCi[48];
    __shared__ float sMax[3], sSum[3];
    const int t = threadIdx.x, lane = t & 31, w = t >> 5;

    for (int i = t; i < 4096; i += 256) {
        int h = i >> 6, d = i & 63;
        sW1[d * 65 + h] = W1[i];
    }
    // assemble Bi: [b][p][0:32]=O1*f1row0, [32:64]=O2*f2row0
    for (int i = t; i < 1536; i += 256) {
        int row = i >> 5, d = i & 31;
        int b = row / 3, p = row - b * 3;
        const float* f1 = (p == 2 ? V : A) + (size_t)b * U * D;
        const float* f2 = (p == 0 ? V : L) + (size_t)b * U * D;
        int pb = (p * BB + b) * D;
        sBi[row * 64 + d]      = g_O1[pb + d] * f1[d];
        sBi[row * 64 + 32 + d] = g_O2[pb + d] * f2[d];
    }
    if (t < 64) { sB1[t] = B1[t]; sW2[t] = W2[t]; }
    __syncthreads();

    for (int rr = 0; rr < 6; rr++) {
        int row = rr * 8 + w;
        float c = 0.f;
#pragma unroll
        for (int hh = 0; hh < 2; hh++) {
            int hid = hh * 32 + lane;
            const float* bi = &sBi[row * 64];
            float a0 = sB1[hid], a1 = 0.f, a2 = 0.f, a3 = 0.f;
#pragma unroll
            for (int dd = 0; dd < 64; dd += 4) {       // 4 independent chains
                a0 += sW1[(dd + 0) * 65 + hid] * bi[dd + 0];
                a1 += sW1[(dd + 1) * 65 + hid] * bi[dd + 1];
                a2 += sW1[(dd + 2) * 65 + hid] * bi[dd + 2];
                a3 += sW1[(dd + 3) * 65 + hid] * bi[dd + 3];
            }
            c += fast_tanh((a0 + a1) + (a2 + a3)) * sW2[hid];
        }
#pragma unroll
        for (int o = 16; o; o >>= 1) c += __shfl_xor_sync(0xffffffffu, c, o);
        if (lane == 0) sCi[row] = c;
    }
    __syncthreads();
    if (t < 3) {
        float m = -1e30f;
        for (int b = 0; b < BB; b++) m = fmaxf(m, sCi[b * 3 + t]);
        float s = 0.f;
        for (int b = 0; b < BB; b++) s += __expf(sCi[b * 3 + t] - m);
        sMax[t] = m; sSum[t] = s;
    }
    __syncthreads();
    for (int it = 0; it < 4; it++) {
        int idx = it * 256 + t;
        int b = idx >> 6, dd = idx & 63;
        float o = 0.f;
#pragma unroll
        for (int k = 0; k < 3; k++) {
            float al = __expf(sCi[b * 3 + k] - sMax[k]) / sSum[k];
            o += al * sBi[(b * 3 + k) * 64 + dd];
        }
        g_CCA[idx] = o;
    }
}

// ---------------- K4: broadcast CCA_i across U ----------------
__global__ void k_bcast(float4* __restrict__ out) {
    int g = blockIdx.x * 256 + threadIdx.x;
    int b = g >> 15;
    int d4 = g & 15;
    out[g] = *(const float4*)&g_CCA[(b * 16 + d4) * 4];
}

// ---------------- launcher ----------------
extern "C" void kernel_launch(void* const* d_in, const int* in_sizes, int n_in,
                              void* d_out, int out_size) {
    (void)in_sizes; (void)n_in; (void)out_size;
    const float* A  = (const float*)d_in[0];
    const float* V  = (const float*)d_in[1];
    const float* L  = (const float*)d_in[2];
    const float* W1 = (const float*)d_in[3];
    const float* B1 = (const float*)d_in[4];
    const float* W2 = (const float*)d_in[5];

    static int smem_set = 0;
    if (!smem_set) {
        cudaFuncSetAttribute(k_main, cudaFuncAttributeMaxDynamicSharedMemorySize,
                             SMEM_TOTAL);
        smem_set = 1;
    }

    k_zero<<<384, 256>>>();
    k_pack<<<dim3(4096, 4), 256>>>(A, V, L);
    k_main<<<dim3(16, 16, 3), 256, SMEM_TOTAL>>>();
    k_stage2<<<dim3(3, 16, 4), 256>>>(A, V, L);
    k_head<<<1, 256>>>(W1, B1, W2, A, V, L);
    k_bcast<<<2048, 256>>>((float4*)d_out);
}